// round 4
// baseline (speedup 1.0000x reference)
#include <cuda_runtime.h>
#include <cuda_bf16.h>
#include <cstdint>

// Problem dims
#define BB    8
#define CTX   4096
#define QST_N 512
#define E_DIM 300
#define H_DIM 128

// Kernel 1 config
#define R1 32            // rows per block
// Kernel 2 config
#define TC    32         // ctx rows per block
#define CHUNK 128        // q rows per smem chunk
#define QPAD  129        // padded row stride for q tile (conflict-free lane stride)

// Scratch (device globals: no allocation allowed in kernel_launch)
__device__ float g_ctx_logits[(size_t)BB * CTX * H_DIM];   // 16 MB
__device__ float g_qst_logits[(size_t)BB * QST_N * H_DIM]; // 2 MB

// ---------------------------------------------------------------------------
// Kernel 1: out[r][h] = ReLU( sum_e x[r][e] * W[h][e] + b[h] )
// Whole W (128x300) + 32-row x tile in shared. 128 threads, thread = h.
// ---------------------------------------------------------------------------
__global__ void logits_kernel(const float* __restrict__ x,
                              const float* __restrict__ W,
                              const float* __restrict__ bias,
                              float* __restrict__ out) {
    extern __shared__ float sm[];
    float* Ws = sm;                       // H_DIM*E_DIM
    float* xs = sm + H_DIM * E_DIM;       // R1*E_DIM

    const int tid = threadIdx.x;          // 128 threads
    const int row0 = blockIdx.x * R1;

    // cooperative loads (float4, everything is 16B aligned: 300*4B rows, row0%32==0)
    const float4* Wg  = (const float4*)W;
    float4*       Ws4 = (float4*)Ws;
    for (int i = tid; i < H_DIM * E_DIM / 4; i += 128) Ws4[i] = Wg[i];

    const float4* xg  = (const float4*)(x + (size_t)row0 * E_DIM);
    float4*       xs4 = (float4*)xs;
    for (int i = tid; i < R1 * E_DIM / 4; i += 128) xs4[i] = xg[i];
    __syncthreads();

    const int h = tid;
    float acc[R1];
    const float bv = bias[h];
#pragma unroll
    for (int r = 0; r < R1; r++) acc[r] = bv;

    const float4* wrow = (const float4*)(Ws + h * E_DIM);
    for (int e4 = 0; e4 < E_DIM / 4; e4++) {
        float4 w = wrow[e4];
#pragma unroll
        for (int r = 0; r < R1; r++) {
            float4 xv = xs4[r * (E_DIM / 4) + e4];   // broadcast across warp
            acc[r] += w.x * xv.x + w.y * xv.y + w.z * xv.z + w.w * xv.w;
        }
    }

#pragma unroll
    for (int r = 0; r < R1; r++)
        out[(size_t)(row0 + r) * H_DIM + h] = fmaxf(acc[r], 0.0f);
}

// ---------------------------------------------------------------------------
// Kernel 2: per block: 32 ctx rows, full 512-wide scores in SMEM,
// softmax(masked), then attn @ qst_logits.  256 threads.
// ---------------------------------------------------------------------------
__global__ void attn_kernel(const float* __restrict__ ctxL,
                            const float* __restrict__ qstL,
                            const int*   __restrict__ mask,
                            float* __restrict__ out) {
    extern __shared__ float sm[];
    float* cs = sm;                               // TC * H_DIM          (16 KB)
    float* qs = cs + TC * H_DIM;                  // CHUNK * QPAD        (64.5 KB)
    float* ss = qs + CHUNK * QPAD;                // TC * QST_N          (64 KB)
    int*   ms = (int*)(ss + TC * QST_N);          // QST_N               (2 KB)

    const int tid  = threadIdx.x;                 // 256
    const int bb   = blockIdx.x >> 7;             // / (CTX/TC)
    const int ct   = blockIdx.x & 127;
    const int row0 = ct * TC;
    const int warp = tid >> 5;
    const int lane = tid & 31;
    const int c0   = warp * 4;                    // 8 warps * 4 rows = 32

    const float* cbase = ctxL + ((size_t)bb * CTX + row0) * H_DIM;
    const float* qbase = qstL + (size_t)bb * QST_N * H_DIM;

    for (int i = tid; i < TC * H_DIM; i += 256) cs[i] = cbase[i];
    for (int i = tid; i < QST_N; i += 256)      ms[i] = mask[bb * QST_N + i];

    // ---------------- Phase 1: scores = ctx_logits @ qst_logits^T ----------
    for (int qc = 0; qc < QST_N / CHUNK; qc++) {
        __syncthreads();   // previous chunk fully consumed (also covers cs/ms init)
        for (int i = tid; i < CHUNK * H_DIM; i += 256) {
            int q = i >> 7, h2 = i & 127;
            qs[q * QPAD + h2] = qbase[(size_t)qc * CHUNK * H_DIM + i];
        }
        __syncthreads();

        float acc[4][4];
#pragma unroll
        for (int i = 0; i < 4; i++)
#pragma unroll
            for (int j = 0; j < 4; j++) acc[i][j] = 0.0f;

        for (int h2 = 0; h2 < H_DIM; h2++) {
            float a0 = cs[(c0 + 0) * H_DIM + h2];          // warp broadcast
            float a1 = cs[(c0 + 1) * H_DIM + h2];
            float a2 = cs[(c0 + 2) * H_DIM + h2];
            float a3 = cs[(c0 + 3) * H_DIM + h2];
            float q0 = qs[(lane +  0) * QPAD + h2];        // conflict-free
            float q1 = qs[(lane + 32) * QPAD + h2];
            float q2 = qs[(lane + 64) * QPAD + h2];
            float q3 = qs[(lane + 96) * QPAD + h2];
            acc[0][0] += a0 * q0; acc[0][1] += a0 * q1; acc[0][2] += a0 * q2; acc[0][3] += a0 * q3;
            acc[1][0] += a1 * q0; acc[1][1] += a1 * q1; acc[1][2] += a1 * q2; acc[1][3] += a1 * q3;
            acc[2][0] += a2 * q0; acc[2][1] += a2 * q1; acc[2][2] += a2 * q2; acc[2][3] += a2 * q3;
            acc[3][0] += a3 * q0; acc[3][1] += a3 * q1; acc[3][2] += a3 * q2; acc[3][3] += a3 * q3;
        }

#pragma unroll
        for (int i = 0; i < 4; i++)
#pragma unroll
            for (int j = 0; j < 4; j++)
                ss[(c0 + i) * QST_N + qc * CHUNK + lane + 32 * j] = acc[i][j];
    }
    __syncthreads();

    // ---------------- Softmax (masked), each warp owns 4 rows --------------
    const float NEG_INF = __int_as_float(0xff800000);
#pragma unroll
    for (int rr = 0; rr < 4; rr++) {
        float* row = ss + (c0 + rr) * QST_N;
        float vals[16];
        float m = NEG_INF;
#pragma unroll
        for (int k = 0; k < 16; k++) {
            float v = row[lane + 32 * k];
            if (ms[lane + 32 * k] == 0) v = NEG_INF;
            vals[k] = v;
            m = fmaxf(m, v);
        }
#pragma unroll
        for (int o = 16; o > 0; o >>= 1) m = fmaxf(m, __shfl_xor_sync(0xffffffffu, m, o));
        float s = 0.0f;
#pragma unroll
        for (int k = 0; k < 16; k++) { float p = expf(vals[k] - m); vals[k] = p; s += p; }
#pragma unroll
        for (int o = 16; o > 0; o >>= 1) s += __shfl_xor_sync(0xffffffffu, s, o);
        float inv = 1.0f / s;
#pragma unroll
        for (int k = 0; k < 16; k++) row[lane + 32 * k] = vals[k] * inv;
    }

    // ---------------- Phase 2: out = attn @ qst_logits ---------------------
    float o[4][4];
#pragma unroll
    for (int i = 0; i < 4; i++)
#pragma unroll
        for (int j = 0; j < 4; j++) o[i][j] = 0.0f;

    for (int qc = 0; qc < QST_N / CHUNK; qc++) {
        __syncthreads();
        for (int i = tid; i < CHUNK * H_DIM; i += 256) {
            int q = i >> 7, h2 = i & 127;
            qs[q * QPAD + h2] = qbase[(size_t)qc * CHUNK * H_DIM + i];
        }
        __syncthreads();

        for (int qq = 0; qq < CHUNK; qq++) {
            int q = qc * CHUNK + qq;
            float a0 = ss[(c0 + 0) * QST_N + q];           // warp broadcast
            float a1 = ss[(c0 + 1) * QST_N + q];
            float a2 = ss[(c0 + 2) * QST_N + q];
            float a3 = ss[(c0 + 3) * QST_N + q];
            float v0 = qs[qq * QPAD + lane +  0];          // conflict-free
            float v1 = qs[qq * QPAD + lane + 32];
            float v2 = qs[qq * QPAD + lane + 64];
            float v3 = qs[qq * QPAD + lane + 96];
            o[0][0] += a0 * v0; o[0][1] += a0 * v1; o[0][2] += a0 * v2; o[0][3] += a0 * v3;
            o[1][0] += a1 * v0; o[1][1] += a1 * v1; o[1][2] += a1 * v2; o[1][3] += a1 * v3;
            o[2][0] += a2 * v0; o[2][1] += a2 * v1; o[2][2] += a2 * v2; o[2][3] += a2 * v3;
            o[3][0] += a3 * v0; o[3][1] += a3 * v1; o[3][2] += a3 * v2; o[3][3] += a3 * v3;
        }
    }

    float* obase = out + ((size_t)bb * CTX + row0) * H_DIM;
#pragma unroll
    for (int i = 0; i < 4; i++)
#pragma unroll
        for (int j = 0; j < 4; j++)
            obase[(size_t)(c0 + i) * H_DIM + lane + 32 * j] = o[i][j];
}

// ---------------------------------------------------------------------------
extern "C" void kernel_launch(void* const* d_in, const int* in_sizes, int n_in,
                              void* d_out, int out_size) {
    const float* ctx  = (const float*)d_in[0];   // [8,4096,300]
    const float* qst  = (const float*)d_in[1];   // [8,512,300]
    const int*   mask = (const int*)d_in[2];     // [8,512]
    const float* W    = (const float*)d_in[3];   // [128,300]
    const float* bias = (const float*)d_in[4];   // [128]
    float*       out  = (float*)d_out;           // [8,4096,128]

    const int smem1 = (H_DIM * E_DIM + R1 * E_DIM) * 4;                       // 192000
    const int smem2 = (TC * H_DIM + CHUNK * QPAD + TC * QST_N) * 4            // 147968
                    + QST_N * 4;                                               // + 2048

    cudaFuncSetAttribute(logits_kernel, cudaFuncAttributeMaxDynamicSharedMemorySize, smem1);
    cudaFuncSetAttribute(attn_kernel,   cudaFuncAttributeMaxDynamicSharedMemorySize, smem2);

    void* p_ctxL = nullptr; void* p_qstL = nullptr;
    cudaGetSymbolAddress(&p_ctxL, g_ctx_logits);
    cudaGetSymbolAddress(&p_qstL, g_qst_logits);
    float* ctxL = (float*)p_ctxL;
    float* qstL = (float*)p_qstL;

    // logits for context (32768 rows) and question (4096 rows)
    logits_kernel<<<(BB * CTX)   / R1, 128, smem1>>>(ctx, W, bias, ctxL);
    logits_kernel<<<(BB * QST_N) / R1, 128, smem1>>>(qst, W, bias, qstL);

    // fused scores -> softmax -> AV
    attn_kernel<<<BB * (CTX / TC), 256, smem2>>>(ctxL, qstL, mask, out);
}

// round 6
// speedup vs baseline: 1.4278x; 1.4278x over previous
#include <cuda_runtime.h>
#include <cuda_bf16.h>
#include <cstdint>

// Problem dims
#define BB    8
#define CTX   4096
#define QST_N 512
#define E_DIM 300
#define H_DIM 128

typedef unsigned long long u64;

// ---- packed f32x2 helpers (sm_103a) ---------------------------------------
__device__ __forceinline__ u64 fma2(u64 a, u64 b, u64 c) {
    u64 d; asm("fma.rn.f32x2 %0, %1, %2, %3;" : "=l"(d) : "l"(a), "l"(b), "l"(c));
    return d;
}
__device__ __forceinline__ u64 mul2(u64 a, u64 b) {
    u64 d; asm("mul.rn.f32x2 %0, %1, %2;" : "=l"(d) : "l"(a), "l"(b));
    return d;
}
__device__ __forceinline__ u64 pack2(float lo, float hi) {
    u64 d; asm("mov.b64 %0, {%1, %2};" : "=l"(d) : "f"(lo), "f"(hi));
    return d;
}
__device__ __forceinline__ float2 unpack2(u64 v) {
    float2 r; asm("mov.b64 {%0, %1}, %2;" : "=f"(r.x), "=f"(r.y) : "l"(v));
    return r;
}

// Scratch (device globals: no allocation allowed in kernel_launch)
__device__ float g_ctx_logits[(size_t)BB * CTX * H_DIM];   // 16 MB
__device__ float g_qst_logits[(size_t)BB * QST_N * H_DIM]; // 2 MB

// ---------------------------------------------------------------------------
// Kernel 1: register-tiled GEMM with f32x2 packed along K.
// out[r][h] = ReLU( sum_e x[r][e] * W[h][e] + b[h] )
// Block: BM=64 rows x 128 h. 256 threads, thread tile 4 rows x 8 h.
// ---------------------------------------------------------------------------
#define BM  64
#define BK  20
#define BKP 22     // padded K stride (even for 8B alignment, conflict-free)

__global__ __launch_bounds__(256) void logits_kernel(const float* __restrict__ x,
                                                     const float* __restrict__ W,
                                                     const float* __restrict__ bias,
                                                     float* __restrict__ out) {
    __shared__ float xs[BM * BKP];      // 5632 B
    __shared__ float ws[H_DIM * BKP];   // 11264 B

    const int tid = threadIdx.x;
    const int tx  = tid & 15;           // h groups: h = tx + 16*j, j<8
    const int ty  = tid >> 4;           // row groups: r = ty*4 + i, i<4
    const int row0 = blockIdx.x * BM;

    u64 acc[4][8];
#pragma unroll
    for (int i = 0; i < 4; i++)
#pragma unroll
        for (int j = 0; j < 8; j++) acc[i][j] = 0ull;

    for (int k0 = 0; k0 < E_DIM; k0 += BK) {
        __syncthreads();
        // load x tile [BM x BK]
        for (int idx = tid; idx < BM * BK; idx += 256) {
            int r = idx / BK, k = idx - r * BK;
            xs[r * BKP + k] = x[(size_t)(row0 + r) * E_DIM + k0 + k];
        }
        // load W tile [128 x BK]
        for (int idx = tid; idx < H_DIM * BK; idx += 256) {
            int h = idx / BK, k = idx - h * BK;
            ws[h * BKP + k] = W[h * E_DIM + k0 + k];
        }
        __syncthreads();

#pragma unroll
        for (int kk = 0; kk < BK; kk += 2) {
            u64 a[4], b[8];
#pragma unroll
            for (int i = 0; i < 4; i++)
                a[i] = *(const u64*)&xs[(ty * 4 + i) * BKP + kk];
#pragma unroll
            for (int j = 0; j < 8; j++)
                b[j] = *(const u64*)&ws[(tx + 16 * j) * BKP + kk];
#pragma unroll
            for (int i = 0; i < 4; i++)
#pragma unroll
                for (int j = 0; j < 8; j++)
                    acc[i][j] = fma2(a[i], b[j], acc[i][j]);
        }
    }

    // epilogue: fold pairs, add bias, ReLU
    float bj[8];
#pragma unroll
    for (int j = 0; j < 8; j++) bj[j] = bias[tx + 16 * j];
#pragma unroll
    for (int i = 0; i < 4; i++) {
        float* orow = out + (size_t)(row0 + ty * 4 + i) * H_DIM;
#pragma unroll
        for (int j = 0; j < 8; j++) {
            float2 s = unpack2(acc[i][j]);
            orow[tx + 16 * j] = fmaxf(s.x + s.y + bj[j], 0.0f);
        }
    }
}

// ---------------------------------------------------------------------------
// Kernel 2: fused flash-attention style. Per block: 32 ctx rows.
// Online softmax over q-chunks of 64; f32x2 packed along the reduction dim
// in both GEMM phases (QK^T packs along h; AV packs along q via transposed V).
// 256 threads, warp owns 4 ctx rows; lane owns q cols {lane, lane+32} and
// h cols {lane+32k, k<4}.
// ---------------------------------------------------------------------------
#define TC2 32
#define CH  64
#define QP  130    // qs row stride: 130 mod 32 = 2 -> conflict-free LDS.64
#define VP  66     // vt row stride: 66  mod 32 = 2 -> conflict-free LDS.64

__global__ __launch_bounds__(256) void attn_kernel(const float* __restrict__ ctxL,
                                                   const float* __restrict__ qstL,
                                                   const int*   __restrict__ mask,
                                                   float* __restrict__ out) {
    extern __shared__ float sm[];
    float* cs = sm;                         // TC2*128      = 4096 floats (16 KB)
    float* qs = cs + TC2 * H_DIM;           // CH*QP        = 8320 floats (32.5 KB)
    float* vt = qs + CH * QP;               // 128*VP       = 8448 floats (33 KB)
    float* ps = vt + H_DIM * VP;            // TC2*CH       = 2048 floats (8 KB)
    // total 22912 floats = 91648 B  -> 2 CTAs / SM

    const int tid  = threadIdx.x;
    const int warp = tid >> 5;
    const int lane = tid & 31;
    const int bb   = blockIdx.x >> 7;
    const int ct   = blockIdx.x & 127;
    const int row0 = ct * TC2;
    const int c0   = warp * 4;

    const float* cbase = ctxL + ((size_t)bb * CTX + row0) * H_DIM;
    const float* qbase = qstL + (size_t)bb * QST_N * H_DIM;
    const int*   mbase = mask + bb * QST_N;

    for (int i = tid; i < TC2 * H_DIM; i += 256) cs[i] = cbase[i];

    const float NEG_INF = __int_as_float(0xff800000);
    float m_i[4], l_i[4];
    u64 o2[4][4];
#pragma unroll
    for (int i = 0; i < 4; i++) {
        m_i[i] = NEG_INF; l_i[i] = 0.0f;
#pragma unroll
        for (int k = 0; k < 4; k++) o2[i][k] = 0ull;
    }

    for (int qc = 0; qc < QST_N / CH; qc++) {
        const int mv0 = mbase[qc * CH + lane];
        const int mv1 = mbase[qc * CH + lane + 32];

        __syncthreads();   // all warps done with previous chunk's qs/vt (covers cs init too)
        for (int i = tid; i < CH * H_DIM; i += 256) {
            int q = i >> 7, h = i & 127;
            float v = qbase[(size_t)qc * CH * H_DIM + i];
            qs[q * QP + h] = v;
            vt[h * VP + q] = v;
        }
        __syncthreads();

        // ---- phase 1: scores tile [4 rows x 2 q-cols], packed along h ----
        u64 acc[4][2];
#pragma unroll
        for (int i = 0; i < 4; i++) { acc[i][0] = 0ull; acc[i][1] = 0ull; }

#pragma unroll 8
        for (int h2 = 0; h2 < H_DIM; h2 += 2) {
            u64 q0 = *(const u64*)&qs[(lane)      * QP + h2];
            u64 q1 = *(const u64*)&qs[(lane + 32) * QP + h2];
#pragma unroll
            for (int i = 0; i < 4; i++) {
                u64 a = *(const u64*)&cs[(c0 + i) * H_DIM + h2];   // warp broadcast
                acc[i][0] = fma2(a, q0, acc[i][0]);
                acc[i][1] = fma2(a, q1, acc[i][1]);
            }
        }

        // ---- online softmax update (per warp, rows c0..c0+3) ----
#pragma unroll
        for (int i = 0; i < 4; i++) {
            float2 s0 = unpack2(acc[i][0]);
            float2 s1 = unpack2(acc[i][1]);
            float v0 = (mv0 == 0) ? NEG_INF : (s0.x + s0.y);
            float v1 = (mv1 == 0) ? NEG_INF : (s1.x + s1.y);
            float mx = fmaxf(v0, v1);
#pragma unroll
            for (int o = 16; o > 0; o >>= 1)
                mx = fmaxf(mx, __shfl_xor_sync(0xffffffffu, mx, o));
            float mn = fmaxf(m_i[i], mx);
            float c  = (m_i[i] == NEG_INF) ? 0.0f : __expf(m_i[i] - mn);
            float p0 = (v0 == NEG_INF) ? 0.0f : __expf(v0 - mn);
            float p1 = (v1 == NEG_INF) ? 0.0f : __expf(v1 - mn);
            float rs = p0 + p1;
#pragma unroll
            for (int o = 16; o > 0; o >>= 1)
                rs += __shfl_xor_sync(0xffffffffu, rs, o);
            l_i[i] = l_i[i] * c + rs;
            m_i[i] = mn;
            u64 cc = pack2(c, c);
#pragma unroll
            for (int k = 0; k < 4; k++) o2[i][k] = mul2(o2[i][k], cc);
            ps[(c0 + i) * CH + lane]      = p0;
            ps[(c0 + i) * CH + lane + 32] = p1;
        }
        __syncwarp();   // ps is warp-private: written & read by this warp only

        // ---- phase 2: o += p @ V, packed along q via transposed V ----
#pragma unroll 8
        for (int q = 0; q < CH; q += 2) {
            u64 vp[4];
#pragma unroll
            for (int k = 0; k < 4; k++)
                vp[k] = *(const u64*)&vt[(lane + 32 * k) * VP + q];
#pragma unroll
            for (int i = 0; i < 4; i++) {
                u64 ap = *(const u64*)&ps[(c0 + i) * CH + q];       // warp broadcast
#pragma unroll
                for (int k = 0; k < 4; k++)
                    o2[i][k] = fma2(ap, vp[k], o2[i][k]);
            }
        }
    }

    // ---- epilogue: fold pairs, normalize ----
    float* obase = out + ((size_t)bb * CTX + row0) * H_DIM;
#pragma unroll
    for (int i = 0; i < 4; i++) {
        float inv = 1.0f / l_i[i];
#pragma unroll
        for (int k = 0; k < 4; k++) {
            float2 t = unpack2(o2[i][k]);
            obase[(size_t)(c0 + i) * H_DIM + lane + 32 * k] = (t.x + t.y) * inv;
        }
    }
}

// ---------------------------------------------------------------------------
extern "C" void kernel_launch(void* const* d_in, const int* in_sizes, int n_in,
                              void* d_out, int out_size) {
    const float* ctx  = (const float*)d_in[0];   // [8,4096,300]
    const float* qst  = (const float*)d_in[1];   // [8,512,300]
    const int*   mask = (const int*)d_in[2];     // [8,512]
    const float* W    = (const float*)d_in[3];   // [128,300]
    const float* bias = (const float*)d_in[4];   // [128]
    float*       out  = (float*)d_out;           // [8,4096,128]

    const int smem2 = (TC2 * H_DIM + CH * QP + H_DIM * VP + TC2 * CH) * 4;  // 91648
    cudaFuncSetAttribute(attn_kernel, cudaFuncAttributeMaxDynamicSharedMemorySize, smem2);

    void* p_ctxL = nullptr; void* p_qstL = nullptr;
    cudaGetSymbolAddress(&p_ctxL, g_ctx_logits);
    cudaGetSymbolAddress(&p_qstL, g_qst_logits);
    float* ctxL = (float*)p_ctxL;
    float* qstL = (float*)p_qstL;

    // logits for context (32768 rows -> 512 blocks) and question (4096 -> 64)
    logits_kernel<<<(BB * CTX)   / BM, 256>>>(ctx, W, bias, ctxL);
    logits_kernel<<<(BB * QST_N) / BM, 256>>>(qst, W, bias, qstL);

    // fused scores -> online softmax -> AV
    attn_kernel<<<BB * (CTX / TC2), 256, smem2>>>(ctxL, qstL, mask, out);
}

// round 7
// speedup vs baseline: 3.2611x; 2.2840x over previous
#include <cuda_runtime.h>
#include <cuda_bf16.h>
#include <cstdint>

// Problem dims
#define BBATCH 8
#define CTX    4096
#define QSTN   512
#define EDIM   300
#define HDIM   128

// Scratch (device globals: no allocation allowed in kernel_launch)
__device__ float g_ctx_logits[(size_t)BBATCH * CTX  * HDIM];   // 16 MB
__device__ float g_qst_logits[(size_t)BBATCH * QSTN * HDIM];   // 2 MB

// ---- tf32 mma helpers -----------------------------------------------------
__device__ __forceinline__ unsigned cvt_tf32(float f) {
    unsigned u; asm("cvt.rna.tf32.f32 %0, %1;" : "=r"(u) : "f"(f)); return u;
}
__device__ __forceinline__ float cvtf_tf32(float f) {
    return __uint_as_float(cvt_tf32(f));
}
// D(16x8,f32) += A(16x8,tf32,row) * B(8x8,tf32,col)
__device__ __forceinline__ void mma8(float& d0, float& d1, float& d2, float& d3,
                                     unsigned a0, unsigned a1, unsigned a2, unsigned a3,
                                     unsigned b0, unsigned b1) {
    asm volatile("mma.sync.aligned.m16n8k8.row.col.f32.tf32.tf32.f32 "
                 "{%0,%1,%2,%3}, {%4,%5,%6,%7}, {%8,%9}, {%0,%1,%2,%3};"
                 : "+f"(d0), "+f"(d1), "+f"(d2), "+f"(d3)
                 : "r"(a0), "r"(a1), "r"(a2), "r"(a3), "r"(b0), "r"(b1));
}

// ---------------------------------------------------------------------------
// Kernel 1: logits = ReLU(x @ W^T + b), 3xTF32 compensated (near-fp32 exact).
// Block: 128 rows x 128 h, 256 threads, 8 warps; warp = 16 rows x 128 h.
// K staged in chunks of 16 (E padded 300->304 with zeros).
// Outputs are rounded to the tf32 grid so the attn kernel's mma reads them
// without further conversion error.
// ---------------------------------------------------------------------------
#define KSP 20   // smem row stride: 20 mod 32 -> conflict-free frag loads

__global__ __launch_bounds__(256) void logits_mma(const float* __restrict__ x,
                                                  const float* __restrict__ W,
                                                  const float* __restrict__ bias,
                                                  float* __restrict__ out) {
    __shared__ float xh[128 * KSP], xl[128 * KSP];
    __shared__ float wh[128 * KSP], wl[128 * KSP];
    __shared__ float bs[HDIM];

    const int tid  = threadIdx.x;
    const int warp = tid >> 5, lane = tid & 31;
    const int rl   = lane >> 2, cl = lane & 3;
    const int row0 = blockIdx.x * 128;
    if (tid < HDIM) bs[tid] = bias[tid];

    float d[16][4];
#pragma unroll
    for (int t = 0; t < 16; t++)
#pragma unroll
        for (int i = 0; i < 4; i++) d[t][i] = 0.0f;

    for (int s = 0; s < 19; s++) {              // 19*16 = 304 >= 300
        const int k0 = s * 16;
        __syncthreads();
        // fill: 1024 float4 (512 x-tile + 512 W-tile); branch uniform per i
#pragma unroll
        for (int i = 0; i < 4; i++) {
            int f = tid + 256 * i;
            const float* src; float* dh; float* dl;
            int r;
            if (f < 512) { r = f >> 2; src = x + (size_t)(row0 + r) * EDIM; dh = xh; dl = xl; }
            else { f -= 512; r = f >> 2; src = W + (size_t)r * EDIM; dh = wh; dl = wl; }
            const int c4 = (f & 3) << 2;
            const int ge = k0 + c4;
            float4 v = make_float4(0.f, 0.f, 0.f, 0.f);
            if (ge + 3 < EDIM) v = *(const float4*)(src + ge);
            float4 h4, l4;
            h4.x = cvtf_tf32(v.x); l4.x = cvtf_tf32(v.x - h4.x);
            h4.y = cvtf_tf32(v.y); l4.y = cvtf_tf32(v.y - h4.y);
            h4.z = cvtf_tf32(v.z); l4.z = cvtf_tf32(v.z - h4.z);
            h4.w = cvtf_tf32(v.w); l4.w = cvtf_tf32(v.w - h4.w);
            *(float4*)(dh + r * KSP + c4) = h4;
            *(float4*)(dl + r * KSP + c4) = l4;
        }
        __syncthreads();

#pragma unroll
        for (int kk = 0; kk < 16; kk += 8) {
            const int ab = (warp * 16 + rl) * KSP + kk + cl;
            unsigned ah0 = __float_as_uint(xh[ab]);
            unsigned ah1 = __float_as_uint(xh[ab + 8 * KSP]);
            unsigned ah2 = __float_as_uint(xh[ab + 4]);
            unsigned ah3 = __float_as_uint(xh[ab + 8 * KSP + 4]);
            unsigned al0 = __float_as_uint(xl[ab]);
            unsigned al1 = __float_as_uint(xl[ab + 8 * KSP]);
            unsigned al2 = __float_as_uint(xl[ab + 4]);
            unsigned al3 = __float_as_uint(xl[ab + 8 * KSP + 4]);
#pragma unroll
            for (int t = 0; t < 16; t++) {
                const int bi = (t * 8 + rl) * KSP + kk + cl;
                unsigned bh0 = __float_as_uint(wh[bi]), bh1 = __float_as_uint(wh[bi + 4]);
                unsigned bl0 = __float_as_uint(wl[bi]), bl1 = __float_as_uint(wl[bi + 4]);
                mma8(d[t][0], d[t][1], d[t][2], d[t][3], ah0, ah1, ah2, ah3, bh0, bh1);
                mma8(d[t][0], d[t][1], d[t][2], d[t][3], ah0, ah1, ah2, ah3, bl0, bl1);
                mma8(d[t][0], d[t][1], d[t][2], d[t][3], al0, al1, al2, al3, bh0, bh1);
            }
        }
    }

    const int rlo = row0 + warp * 16 + rl;
    const int rhi = rlo + 8;
#pragma unroll
    for (int t = 0; t < 16; t++) {
        const int c0 = t * 8 + 2 * cl;
        const float b0 = bs[c0], b1 = bs[c0 + 1];
        float2 v0, v1;
        v0.x = cvtf_tf32(fmaxf(d[t][0] + b0, 0.0f));
        v0.y = cvtf_tf32(fmaxf(d[t][1] + b1, 0.0f));
        v1.x = cvtf_tf32(fmaxf(d[t][2] + b0, 0.0f));
        v1.y = cvtf_tf32(fmaxf(d[t][3] + b1, 0.0f));
        *(float2*)(out + (size_t)rlo * HDIM + c0) = v0;
        *(float2*)(out + (size_t)rhi * HDIM + c0) = v1;
    }
}

// ---------------------------------------------------------------------------
// Kernel 2: fused flash attention with tf32 mma.
// Block: 64 ctx rows, 128 threads (4 warps); warp = 16 rows, full width.
// Chunks of 64 q: phase1 S = C@Q^T (mma), warp-local masked online softmax
// on fragments, P->tf32->smem (C-frag -> A-frag relayout), phase2 O += P@V.
// smem strides: cs 132 (mod32=4: phase1 A ok), qs 136 (mod32=8: phase2 B
// conflict-free; phase1 B 2-way, accepted), ps 68 (mod32=4: phase2 A ok).
// ---------------------------------------------------------------------------
#define CSP 132
#define QSP 136
#define PSP 68
#define ATTN_SMEM ((64 * CSP + 64 * QSP + 64 * PSP) * 4 + QSTN * 4)   // 88064 B

__global__ __launch_bounds__(128) void attn_mma(const float* __restrict__ ctxL,
                                                const float* __restrict__ qstL,
                                                const int*   __restrict__ mask,
                                                float* __restrict__ out) {
    extern __shared__ float sm[];
    float* cs = sm;                    // 64 x 132
    float* qs = cs + 64 * CSP;         // 64 x 136  (Q and V view of the chunk)
    float* ps = qs + 64 * QSP;         // 64 x 68   (P, warp-private rows)
    int*   ms = (int*)(ps + 64 * PSP); // 512

    const int tid  = threadIdx.x;
    const int warp = tid >> 5, lane = tid & 31;
    const int rl   = lane >> 2, cl = lane & 3;
    const int bb   = blockIdx.x >> 6;
    const int ct   = blockIdx.x & 63;
    const int row0 = ct * 64;
    const int r0   = warp * 16;

    const float* cbase = ctxL + ((size_t)bb * CTX + row0) * HDIM;
    const float* qbase = qstL + (size_t)bb * QSTN * HDIM;

    // fill cs (values already tf32-grid from logits epilogue) + mask
    for (int f = tid; f < 2048; f += 128) {
        const int r = f >> 5, h4 = (f & 31) << 2;
        *(float4*)(cs + r * CSP + h4) = *(const float4*)(cbase + (size_t)r * HDIM + h4);
    }
    for (int i = tid; i < QSTN; i += 128) ms[i] = mask[bb * QSTN + i];

    const float NEG_INF = __int_as_float(0xff800000);
    float o[16][4];
#pragma unroll
    for (int t = 0; t < 16; t++)
#pragma unroll
        for (int i = 0; i < 4; i++) o[t][i] = 0.0f;
    float m_lo = NEG_INF, m_hi = NEG_INF, l_lo = 0.0f, l_hi = 0.0f;

    for (int qc = 0; qc < QSTN / 64; qc++) {
        __syncthreads();               // previous chunk fully consumed
        for (int f = tid; f < 2048; f += 128) {
            const int q = f >> 5, h4 = (f & 31) << 2;
            *(float4*)(qs + q * QSP + h4) =
                *(const float4*)(qbase + (size_t)qc * 64 * HDIM + (size_t)q * HDIM + h4);
        }
        __syncthreads();

        // ---- phase 1: S[16 x 64] = C @ Q^T -------------------------------
        float s[8][4];
#pragma unroll
        for (int t = 0; t < 8; t++)
#pragma unroll
            for (int i = 0; i < 4; i++) s[t][i] = 0.0f;

#pragma unroll
        for (int k0 = 0; k0 < HDIM; k0 += 8) {
            const int ab = (r0 + rl) * CSP + k0 + cl;
            unsigned a0 = __float_as_uint(cs[ab]);
            unsigned a1 = __float_as_uint(cs[ab + 8 * CSP]);
            unsigned a2 = __float_as_uint(cs[ab + 4]);
            unsigned a3 = __float_as_uint(cs[ab + 8 * CSP + 4]);
#pragma unroll
            for (int t = 0; t < 8; t++) {
                const int bi = (t * 8 + rl) * QSP + k0 + cl;
                unsigned b0 = __float_as_uint(qs[bi]);
                unsigned b1 = __float_as_uint(qs[bi + 4]);
                mma8(s[t][0], s[t][1], s[t][2], s[t][3], a0, a1, a2, a3, b0, b1);
            }
        }

        // ---- masked online softmax (warp-local; rows rl, rl+8) -----------
        const int qb = qc * 64;
        float mx_lo = NEG_INF, mx_hi = NEG_INF;
#pragma unroll
        for (int t = 0; t < 8; t++) {
            const int c0 = t * 8 + 2 * cl;
            const int m0 = ms[qb + c0], m1 = ms[qb + c0 + 1];
            if (m0) { mx_lo = fmaxf(mx_lo, s[t][0]); mx_hi = fmaxf(mx_hi, s[t][2]); }
            if (m1) { mx_lo = fmaxf(mx_lo, s[t][1]); mx_hi = fmaxf(mx_hi, s[t][3]); }
        }
#pragma unroll
        for (int off = 1; off <= 2; off <<= 1) {
            mx_lo = fmaxf(mx_lo, __shfl_xor_sync(0xffffffffu, mx_lo, off));
            mx_hi = fmaxf(mx_hi, __shfl_xor_sync(0xffffffffu, mx_hi, off));
        }
        const float mn_lo = fmaxf(m_lo, mx_lo);
        const float mn_hi = fmaxf(m_hi, mx_hi);
        const float sc_lo = (m_lo == NEG_INF) ? 0.0f : __expf(m_lo - mn_lo);
        const float sc_hi = (m_hi == NEG_INF) ? 0.0f : __expf(m_hi - mn_hi);

        float sum_lo = 0.0f, sum_hi = 0.0f;
#pragma unroll
        for (int t = 0; t < 8; t++) {
            const int c0 = t * 8 + 2 * cl;
            const int m0 = ms[qb + c0], m1 = ms[qb + c0 + 1];
            float p0 = m0 ? cvtf_tf32(__expf(s[t][0] - mn_lo)) : 0.0f;
            float p1 = m1 ? cvtf_tf32(__expf(s[t][1] - mn_lo)) : 0.0f;
            float p2 = m0 ? cvtf_tf32(__expf(s[t][2] - mn_hi)) : 0.0f;
            float p3 = m1 ? cvtf_tf32(__expf(s[t][3] - mn_hi)) : 0.0f;
            sum_lo += p0 + p1;
            sum_hi += p2 + p3;
            *(float2*)(ps + (r0 + rl) * PSP + c0)     = make_float2(p0, p1);
            *(float2*)(ps + (r0 + 8 + rl) * PSP + c0) = make_float2(p2, p3);
        }
#pragma unroll
        for (int off = 1; off <= 2; off <<= 1) {
            sum_lo += __shfl_xor_sync(0xffffffffu, sum_lo, off);
            sum_hi += __shfl_xor_sync(0xffffffffu, sum_hi, off);
        }
        l_lo = l_lo * sc_lo + sum_lo;
        l_hi = l_hi * sc_hi + sum_hi;
        m_lo = mn_lo; m_hi = mn_hi;

#pragma unroll
        for (int t = 0; t < 16; t++) {
            o[t][0] *= sc_lo; o[t][1] *= sc_lo;
            o[t][2] *= sc_hi; o[t][3] *= sc_hi;
        }
        __syncwarp();   // ps rows are warp-private; order STS -> cross-lane LDS

        // ---- phase 2: O[16 x 128] += P @ V -------------------------------
#pragma unroll
        for (int k0 = 0; k0 < 64; k0 += 8) {
            const int ab = (r0 + rl) * PSP + k0 + cl;
            unsigned a0 = __float_as_uint(ps[ab]);
            unsigned a1 = __float_as_uint(ps[ab + 8 * PSP]);
            unsigned a2 = __float_as_uint(ps[ab + 4]);
            unsigned a3 = __float_as_uint(ps[ab + 8 * PSP + 4]);
#pragma unroll
            for (int t = 0; t < 16; t++) {
                const int bi = (k0 + cl) * QSP + t * 8 + rl;
                unsigned b0 = __float_as_uint(qs[bi]);
                unsigned b1 = __float_as_uint(qs[bi + 4 * QSP]);
                mma8(o[t][0], o[t][1], o[t][2], o[t][3], a0, a1, a2, a3, b0, b1);
            }
        }
    }

    // ---- epilogue: normalize + store ------------------------------------
    const float inv_lo = 1.0f / l_lo;
    const float inv_hi = 1.0f / l_hi;
    float* ob = out + ((size_t)bb * CTX + row0) * HDIM;
    const int rlo = r0 + rl, rhi = rlo + 8;
#pragma unroll
    for (int t = 0; t < 16; t++) {
        const int c0 = t * 8 + 2 * cl;
        *(float2*)(ob + (size_t)rlo * HDIM + c0) =
            make_float2(o[t][0] * inv_lo, o[t][1] * inv_lo);
        *(float2*)(ob + (size_t)rhi * HDIM + c0) =
            make_float2(o[t][2] * inv_hi, o[t][3] * inv_hi);
    }
}

// ---------------------------------------------------------------------------
extern "C" void kernel_launch(void* const* d_in, const int* in_sizes, int n_in,
                              void* d_out, int out_size) {
    const float* ctx  = (const float*)d_in[0];   // [8,4096,300]
    const float* qst  = (const float*)d_in[1];   // [8,512,300]
    const int*   mask = (const int*)d_in[2];     // [8,512]
    const float* W    = (const float*)d_in[3];   // [128,300]
    const float* bias = (const float*)d_in[4];   // [128]
    float*       out  = (float*)d_out;           // [8,4096,128]

    cudaFuncSetAttribute(attn_mma, cudaFuncAttributeMaxDynamicSharedMemorySize, ATTN_SMEM);

    void* p_ctxL = nullptr; void* p_qstL = nullptr;
    cudaGetSymbolAddress(&p_ctxL, g_ctx_logits);
    cudaGetSymbolAddress(&p_qstL, g_qst_logits);
    float* ctxL = (float*)p_ctxL;
    float* qstL = (float*)p_qstL;

    // logits: ctx 32768 rows -> 256 blocks; qst 4096 rows -> 32 blocks
    logits_mma<<<(BBATCH * CTX)  / 128, 256>>>(ctx, W, bias, ctxL);
    logits_mma<<<(BBATCH * QSTN) / 128, 256>>>(qst, W, bias, qstL);

    // fused scores -> online softmax -> AV (64 ctx rows per block)
    attn_mma<<<BBATCH * (CTX / 64), 128, ATTN_SMEM>>>(ctxL, qstL, mask, out);
}

// round 10
// speedup vs baseline: 3.4177x; 1.0480x over previous
#include <cuda_runtime.h>
#include <cuda_bf16.h>
#include <cstdint>

// Problem dims
#define BBATCH 8
#define CTX    4096
#define QSTN   512
#define EDIM   300
#define HDIM   128

// Scratch (device globals: no allocation allowed in kernel_launch)
__device__ float g_ctx_logits[(size_t)BBATCH * CTX  * HDIM];   // 16 MB
__device__ float g_qst_logits[(size_t)BBATCH * QSTN * HDIM];   // 2 MB

// ---- tf32 mma helpers -----------------------------------------------------
__device__ __forceinline__ unsigned cvt_tf32(float f) {
    unsigned u; asm("cvt.rna.tf32.f32 %0, %1;" : "=r"(u) : "f"(f)); return u;
}
__device__ __forceinline__ float cvtf_tf32(float f) {
    return __uint_as_float(cvt_tf32(f));
}
// D(16x8,f32) += A(16x8,tf32,row) * B(8x8,tf32,col)
__device__ __forceinline__ void mma8(float& d0, float& d1, float& d2, float& d3,
                                     unsigned a0, unsigned a1, unsigned a2, unsigned a3,
                                     unsigned b0, unsigned b1) {
    asm volatile("mma.sync.aligned.m16n8k8.row.col.f32.tf32.tf32.f32 "
                 "{%0,%1,%2,%3}, {%4,%5,%6,%7}, {%8,%9}, {%0,%1,%2,%3};"
                 : "+f"(d0), "+f"(d1), "+f"(d2), "+f"(d3)
                 : "r"(a0), "r"(a1), "r"(a2), "r"(a3), "r"(b0), "r"(b1));
}

// ---------------------------------------------------------------------------
// Kernel 1: logits = ReLU(x @ W^T + b), 3xTF32 compensated (near-fp32 exact).
// (unchanged from R6 — 60us, tensor=41.6%)
// ---------------------------------------------------------------------------
#define KSP 20   // smem row stride: 20 mod 32 -> conflict-free frag loads

__global__ __launch_bounds__(256) void logits_mma(const float* __restrict__ x,
                                                  const float* __restrict__ W,
                                                  const float* __restrict__ bias,
                                                  float* __restrict__ out) {
    __shared__ float xh[128 * KSP], xl[128 * KSP];
    __shared__ float wh[128 * KSP], wl[128 * KSP];
    __shared__ float bs[HDIM];

    const int tid  = threadIdx.x;
    const int warp = tid >> 5, lane = tid & 31;
    const int rl   = lane >> 2, cl = lane & 3;
    const int row0 = blockIdx.x * 128;
    if (tid < HDIM) bs[tid] = bias[tid];

    float d[16][4];
#pragma unroll
    for (int t = 0; t < 16; t++)
#pragma unroll
        for (int i = 0; i < 4; i++) d[t][i] = 0.0f;

    for (int s = 0; s < 19; s++) {              // 19*16 = 304 >= 300
        const int k0 = s * 16;
        __syncthreads();
#pragma unroll
        for (int i = 0; i < 4; i++) {
            int f = tid + 256 * i;
            const float* src; float* dh; float* dl;
            int r;
            if (f < 512) { r = f >> 2; src = x + (size_t)(row0 + r) * EDIM; dh = xh; dl = xl; }
            else { f -= 512; r = f >> 2; src = W + (size_t)r * EDIM; dh = wh; dl = wl; }
            const int c4 = (f & 3) << 2;
            const int ge = k0 + c4;
            float4 v = make_float4(0.f, 0.f, 0.f, 0.f);
            if (ge + 3 < EDIM) v = *(const float4*)(src + ge);
            float4 h4, l4;
            h4.x = cvtf_tf32(v.x); l4.x = cvtf_tf32(v.x - h4.x);
            h4.y = cvtf_tf32(v.y); l4.y = cvtf_tf32(v.y - h4.y);
            h4.z = cvtf_tf32(v.z); l4.z = cvtf_tf32(v.z - h4.z);
            h4.w = cvtf_tf32(v.w); l4.w = cvtf_tf32(v.w - h4.w);
            *(float4*)(dh + r * KSP + c4) = h4;
            *(float4*)(dl + r * KSP + c4) = l4;
        }
        __syncthreads();

#pragma unroll
        for (int kk = 0; kk < 16; kk += 8) {
            const int ab = (warp * 16 + rl) * KSP + kk + cl;
            unsigned ah0 = __float_as_uint(xh[ab]);
            unsigned ah1 = __float_as_uint(xh[ab + 8 * KSP]);
            unsigned ah2 = __float_as_uint(xh[ab + 4]);
            unsigned ah3 = __float_as_uint(xh[ab + 8 * KSP + 4]);
            unsigned al0 = __float_as_uint(xl[ab]);
            unsigned al1 = __float_as_uint(xl[ab + 8 * KSP]);
            unsigned al2 = __float_as_uint(xl[ab + 4]);
            unsigned al3 = __float_as_uint(xl[ab + 8 * KSP + 4]);
#pragma unroll
            for (int t = 0; t < 16; t++) {
                const int bi = (t * 8 + rl) * KSP + kk + cl;
                unsigned bh0 = __float_as_uint(wh[bi]), bh1 = __float_as_uint(wh[bi + 4]);
                unsigned bl0 = __float_as_uint(wl[bi]), bl1 = __float_as_uint(wl[bi + 4]);
                mma8(d[t][0], d[t][1], d[t][2], d[t][3], ah0, ah1, ah2, ah3, bh0, bh1);
                mma8(d[t][0], d[t][1], d[t][2], d[t][3], ah0, ah1, ah2, ah3, bl0, bl1);
                mma8(d[t][0], d[t][1], d[t][2], d[t][3], al0, al1, al2, al3, bh0, bh1);
            }
        }
    }

    const int rlo = row0 + warp * 16 + rl;
    const int rhi = rlo + 8;
#pragma unroll
    for (int t = 0; t < 16; t++) {
        const int c0 = t * 8 + 2 * cl;
        const float b0 = bs[c0], b1 = bs[c0 + 1];
        float2 v0, v1;
        v0.x = cvtf_tf32(fmaxf(d[t][0] + b0, 0.0f));
        v0.y = cvtf_tf32(fmaxf(d[t][1] + b1, 0.0f));
        v1.x = cvtf_tf32(fmaxf(d[t][2] + b0, 0.0f));
        v1.y = cvtf_tf32(fmaxf(d[t][3] + b1, 0.0f));
        *(float2*)(out + (size_t)rlo * HDIM + c0) = v0;
        *(float2*)(out + (size_t)rhi * HDIM + c0) = v1;
    }
}

// ---------------------------------------------------------------------------
// Kernel 2: fused flash attention, tf32 mma, WARP-PAIR split.
// Block: 64 ctx rows, 256 threads (8 warps = 4 pairs). Pair owns 16 rows.
// Within a pair: phase1 splits the 64-q chunk (32 q per warp), phase2 splits
// h (64 per warp). Partial row-max / row-sum exchanged via smem + named
// pair barrier. Persistent regs per warp: o[8][4]=32 (vs 64 before).
// ---------------------------------------------------------------------------
#define CSP 132   // mod 32 = 4 -> A frags conflict-free
#define QSP 136   // mod 32 = 8 -> phase2 B conflict-free, phase1 B 2-way (ok)
#define PSP 68    // mod 32 = 4 -> phase2 A conflict-free
// floats: cs 64*132=8448, qs 64*136=8704, ps 4*16*68=4352, red 256 -> 21760
#define ATTN_SMEM (21760 * 4 + QSTN * 4)   // 89088 B -> 2 CTAs/SM

__global__ __launch_bounds__(256, 2) void attn_mma(const float* __restrict__ ctxL,
                                                   const float* __restrict__ qstL,
                                                   const int*   __restrict__ mask,
                                                   float* __restrict__ out) {
    extern __shared__ float sm[];
    float* cs   = sm;                     // 64 x 132
    float* qs   = cs + 64 * CSP;          // 64 x 136 (Q and V view of chunk)
    float* ps   = qs + 64 * QSP;          // [4 pairs][16 rows][68]
    float* redm = ps + 4 * 16 * PSP;      // [4][2][16] partial row max
    float* reds = redm + 128;             // [4][2][16] partial row sum
    int*   ms   = (int*)(reds + 128);     // 512

    const int tid  = threadIdx.x;
    const int warp = tid >> 5, lane = tid & 31;
    const int rl   = lane >> 2, cl = lane & 3;
    const int pair = warp >> 1, half = warp & 1;
    const int bb   = blockIdx.x >> 6;
    const int ct   = blockIdx.x & 63;
    const int row0 = ct * 64;
    const int r0   = pair * 16;           // pair's rows within block
    float* pr = ps + pair * 16 * PSP;

    const float* cbase = ctxL + ((size_t)bb * CTX + row0) * HDIM;
    const float* qbase = qstL + (size_t)bb * QSTN * HDIM;

    for (int f = tid; f < 2048; f += 256) {
        const int r = f >> 5, h4 = (f & 31) << 2;
        *(float4*)(cs + r * CSP + h4) = *(const float4*)(cbase + (size_t)r * HDIM + h4);
    }
    for (int i = tid; i < QSTN; i += 256) ms[i] = mask[bb * QSTN + i];

    const float NEG_INF = __int_as_float(0xff800000);
    float o[8][4];
#pragma unroll
    for (int t = 0; t < 8; t++)
#pragma unroll
        for (int i = 0; i < 4; i++) o[t][i] = 0.0f;
    float m_lo = NEG_INF, m_hi = NEG_INF, l_lo = 0.0f, l_hi = 0.0f;

    for (int qc = 0; qc < QSTN / 64; qc++) {
        __syncthreads();               // previous chunk fully consumed (qs, ps, red)
        for (int f = tid; f < 2048; f += 256) {
            const int q = f >> 5, h4 = (f & 31) << 2;
            *(float4*)(qs + q * QSP + h4) =
                *(const float4*)(qbase + (size_t)qc * 64 * HDIM + (size_t)q * HDIM + h4);
        }
        __syncthreads();

        // ---- phase 1: S[16 x 32] = C @ Q^T (this warp's q half) ----------
        float s[4][4];
#pragma unroll
        for (int t = 0; t < 4; t++)
#pragma unroll
            for (int i = 0; i < 4; i++) s[t][i] = 0.0f;

#pragma unroll
        for (int k0 = 0; k0 < HDIM; k0 += 8) {
            const int ab = (r0 + rl) * CSP + k0 + cl;
            unsigned a0 = __float_as_uint(cs[ab]);
            unsigned a1 = __float_as_uint(cs[ab + 8 * CSP]);
            unsigned a2 = __float_as_uint(cs[ab + 4]);
            unsigned a3 = __float_as_uint(cs[ab + 8 * CSP + 4]);
#pragma unroll
            for (int t = 0; t < 4; t++) {
                const int bi = (half * 32 + t * 8 + rl) * QSP + k0 + cl;
                unsigned b0 = __float_as_uint(qs[bi]);
                unsigned b1 = __float_as_uint(qs[bi + 4]);
                mma8(s[t][0], s[t][1], s[t][2], s[t][3], a0, a1, a2, a3, b0, b1);
            }
        }

        // ---- masked partial row max over this half -----------------------
        const int qb = qc * 64 + half * 32;
        float mx_lo = NEG_INF, mx_hi = NEG_INF;
#pragma unroll
        for (int t = 0; t < 4; t++) {
            const int c0 = t * 8 + 2 * cl;
            const int m0 = ms[qb + c0], m1 = ms[qb + c0 + 1];
            if (m0) { mx_lo = fmaxf(mx_lo, s[t][0]); mx_hi = fmaxf(mx_hi, s[t][2]); }
            if (m1) { mx_lo = fmaxf(mx_lo, s[t][1]); mx_hi = fmaxf(mx_hi, s[t][3]); }
        }
#pragma unroll
        for (int off = 1; off <= 2; off <<= 1) {
            mx_lo = fmaxf(mx_lo, __shfl_xor_sync(0xffffffffu, mx_lo, off));
            mx_hi = fmaxf(mx_hi, __shfl_xor_sync(0xffffffffu, mx_hi, off));
        }
        // exchange with partner half
        if (cl == 0) {
            redm[(pair * 2 + half) * 16 + rl]     = mx_lo;
            redm[(pair * 2 + half) * 16 + rl + 8] = mx_hi;
        }
        asm volatile("bar.sync %0, 64;" :: "r"(pair + 1) : "memory");
        mx_lo = fmaxf(mx_lo, redm[(pair * 2 + (1 - half)) * 16 + rl]);
        mx_hi = fmaxf(mx_hi, redm[(pair * 2 + (1 - half)) * 16 + rl + 8]);

        const float mn_lo = fmaxf(m_lo, mx_lo);
        const float mn_hi = fmaxf(m_hi, mx_hi);
        const float sc_lo = (m_lo == NEG_INF) ? 0.0f : __expf(m_lo - mn_lo);
        const float sc_hi = (m_hi == NEG_INF) ? 0.0f : __expf(m_hi - mn_hi);

        // ---- exp, P -> smem (this half's cols), partial sums -------------
        float sum_lo = 0.0f, sum_hi = 0.0f;
#pragma unroll
        for (int t = 0; t < 4; t++) {
            const int c0 = t * 8 + 2 * cl;
            const int m0 = ms[qb + c0], m1 = ms[qb + c0 + 1];
            float p0 = m0 ? cvtf_tf32(__expf(s[t][0] - mn_lo)) : 0.0f;
            float p1 = m1 ? cvtf_tf32(__expf(s[t][1] - mn_lo)) : 0.0f;
            float p2 = m0 ? cvtf_tf32(__expf(s[t][2] - mn_hi)) : 0.0f;
            float p3 = m1 ? cvtf_tf32(__expf(s[t][3] - mn_hi)) : 0.0f;
            sum_lo += p0 + p1;
            sum_hi += p2 + p3;
            const int col = half * 32 + c0;
            *(float2*)(pr + rl * PSP + col)       = make_float2(p0, p1);
            *(float2*)(pr + (rl + 8) * PSP + col) = make_float2(p2, p3);
        }
#pragma unroll
        for (int off = 1; off <= 2; off <<= 1) {
            sum_lo += __shfl_xor_sync(0xffffffffu, sum_lo, off);
            sum_hi += __shfl_xor_sync(0xffffffffu, sum_hi, off);
        }
        if (cl == 0) {
            reds[(pair * 2 + half) * 16 + rl]     = sum_lo;
            reds[(pair * 2 + half) * 16 + rl + 8] = sum_hi;
        }
        asm volatile("bar.sync %0, 64;" :: "r"(pair + 1) : "memory");  // also orders ps
        sum_lo += reds[(pair * 2 + (1 - half)) * 16 + rl];
        sum_hi += reds[(pair * 2 + (1 - half)) * 16 + rl + 8];

        l_lo = l_lo * sc_lo + sum_lo;
        l_hi = l_hi * sc_hi + sum_hi;
        m_lo = mn_lo; m_hi = mn_hi;

#pragma unroll
        for (int t = 0; t < 8; t++) {
            o[t][0] *= sc_lo; o[t][1] *= sc_lo;
            o[t][2] *= sc_hi; o[t][3] *= sc_hi;
        }

        // ---- phase 2: O[16 x 64] += P @ V (this warp's h half) -----------
#pragma unroll
        for (int k0 = 0; k0 < 64; k0 += 8) {
            const int ab = rl * PSP + k0 + cl;
            unsigned a0 = __float_as_uint(pr[ab]);
            unsigned a1 = __float_as_uint(pr[ab + 8 * PSP]);
            unsigned a2 = __float_as_uint(pr[ab + 4]);
            unsigned a3 = __float_as_uint(pr[ab + 8 * PSP + 4]);
#pragma unroll
            for (int t = 0; t < 8; t++) {
                const int bi = (k0 + cl) * QSP + half * 64 + t * 8 + rl;
                unsigned b0 = __float_as_uint(qs[bi]);
                unsigned b1 = __float_as_uint(qs[bi + 4 * QSP]);
                mma8(o[t][0], o[t][1], o[t][2], o[t][3], a0, a1, a2, a3, b0, b1);
            }
        }
    }

    // ---- epilogue: normalize + store -------------------------------------
    const float inv_lo = 1.0f / l_lo;
    const float inv_hi = 1.0f / l_hi;
    float* ob = out + ((size_t)bb * CTX + row0) * HDIM;
    const int rlo = r0 + rl, rhi = rlo + 8;
#pragma unroll
    for (int t = 0; t < 8; t++) {
        const int c0 = half * 64 + t * 8 + 2 * cl;
        *(float2*)(ob + (size_t)rlo * HDIM + c0) =
            make_float2(o[t][0] * inv_lo, o[t][1] * inv_lo);
        *(float2*)(ob + (size_t)rhi * HDIM + c0) =
            make_float2(o[t][2] * inv_hi, o[t][3] * inv_hi);
    }
}

// ---------------------------------------------------------------------------
extern "C" void kernel_launch(void* const* d_in, const int* in_sizes, int n_in,
                              void* d_out, int out_size) {
    const float* ctx  = (const float*)d_in[0];   // [8,4096,300]
    const float* qst  = (const float*)d_in[1];   // [8,512,300]
    const int*   mask = (const int*)d_in[2];     // [8,512]
    const float* W    = (const float*)d_in[3];   // [128,300]
    const float* bias = (const float*)d_in[4];   // [128]
    float*       out  = (float*)d_out;           // [8,4096,128]

    cudaFuncSetAttribute(attn_mma, cudaFuncAttributeMaxDynamicSharedMemorySize, ATTN_SMEM);

    void* p_ctxL = nullptr; void* p_qstL = nullptr;
    cudaGetSymbolAddress(&p_ctxL, g_ctx_logits);
    cudaGetSymbolAddress(&p_qstL, g_qst_logits);
    float* ctxL = (float*)p_ctxL;
    float* qstL = (float*)p_qstL;

    // logits: ctx 32768 rows -> 256 blocks; qst 4096 rows -> 32 blocks
    logits_mma<<<(BBATCH * CTX)  / 128, 256>>>(ctx, W, bias, ctxL);
    logits_mma<<<(BBATCH * QSTN) / 128, 256>>>(qst, W, bias, qstL);

    // fused scores -> online softmax -> AV (64 ctx rows, 8 warps per block)
    attn_mma<<<BBATCH * (CTX / 64), 256, ATTN_SMEM>>>(ctxL, qstL, mask, out);
}

// round 11
// speedup vs baseline: 4.7235x; 1.3821x over previous
#include <cuda_runtime.h>
#include <cuda_bf16.h>
#include <cstdint>

// Problem dims
#define BBATCH 8
#define CTX    4096
#define QSTN   512
#define EDIM   300
#define HDIM   128

// Scratch (device globals: no allocation allowed in kernel_launch)
__device__ float g_ctx_logits[(size_t)BBATCH * CTX  * HDIM];   // 16 MB
__device__ float g_qst_logits[(size_t)BBATCH * QSTN * HDIM];   // 2 MB

// ---- tf32 mma helpers -----------------------------------------------------
__device__ __forceinline__ unsigned cvt_tf32(float f) {
    unsigned u; asm("cvt.rna.tf32.f32 %0, %1;" : "=r"(u) : "f"(f)); return u;
}
__device__ __forceinline__ float cvtf_tf32(float f) {
    return __uint_as_float(cvt_tf32(f));
}
// D(16x8,f32) += A(16x8,tf32,row) * B(8x8,tf32,col)
__device__ __forceinline__ void mma8(float& d0, float& d1, float& d2, float& d3,
                                     unsigned a0, unsigned a1, unsigned a2, unsigned a3,
                                     unsigned b0, unsigned b1) {
    asm volatile("mma.sync.aligned.m16n8k8.row.col.f32.tf32.tf32.f32 "
                 "{%0,%1,%2,%3}, {%4,%5,%6,%7}, {%8,%9}, {%0,%1,%2,%3};"
                 : "+f"(d0), "+f"(d1), "+f"(d2), "+f"(d3)
                 : "r"(a0), "r"(a1), "r"(a2), "r"(a3), "r"(b0), "r"(b1));
}

// ---------------------------------------------------------------------------
// Kernel 1: logits = ReLU(x @ W^T + b), 2xTF32 compensated:
//   d = (xh + xl) * Wh  (exact x times tf32-rounded W; rel err ~1e-4)
// Fused grid: blocks [0,256) -> ctx rows, [256,288) -> qst rows.
// Block: 128 rows x 128 h, 256 threads, 8 warps; warp = 16 rows x 128 h.
// ---------------------------------------------------------------------------
#define KSP 20   // smem row stride: 20 mod 32 -> conflict-free frag loads

__global__ __launch_bounds__(256) void logits_mma(const float* __restrict__ ctx,
                                                  const float* __restrict__ qst,
                                                  const float* __restrict__ W,
                                                  const float* __restrict__ bias,
                                                  float* __restrict__ ctxL,
                                                  float* __restrict__ qstL) {
    __shared__ float xh[128 * KSP], xl[128 * KSP];
    __shared__ float wh[128 * KSP];
    __shared__ float bs[HDIM];

    const int tid  = threadIdx.x;
    const int warp = tid >> 5, lane = tid & 31;
    const int rl   = lane >> 2, cl = lane & 3;

    const bool is_ctx = (blockIdx.x < 256);
    const int  row0   = (is_ctx ? blockIdx.x : (blockIdx.x - 256)) * 128;
    const float* x    = is_ctx ? ctx  : qst;
    float*       out  = is_ctx ? ctxL : qstL;

    if (tid < HDIM) bs[tid] = bias[tid];

    float d[16][4];
#pragma unroll
    for (int t = 0; t < 16; t++)
#pragma unroll
        for (int i = 0; i < 4; i++) d[t][i] = 0.0f;

    for (int s = 0; s < 19; s++) {              // 19*16 = 304 >= 300
        const int k0 = s * 16;
        __syncthreads();
        // fill: 1024 float4 slots (512 x-tile hi/lo + 512 W-tile hi only)
#pragma unroll
        for (int i = 0; i < 4; i++) {
            int f = tid + 256 * i;
            if (f < 512) {
                const int r  = f >> 2;
                const int c4 = (f & 3) << 2;
                const int ge = k0 + c4;
                float4 v = make_float4(0.f, 0.f, 0.f, 0.f);
                if (ge + 3 < EDIM) v = *(const float4*)(x + (size_t)(row0 + r) * EDIM + ge);
                float4 h4, l4;
                h4.x = cvtf_tf32(v.x); l4.x = cvtf_tf32(v.x - h4.x);
                h4.y = cvtf_tf32(v.y); l4.y = cvtf_tf32(v.y - h4.y);
                h4.z = cvtf_tf32(v.z); l4.z = cvtf_tf32(v.z - h4.z);
                h4.w = cvtf_tf32(v.w); l4.w = cvtf_tf32(v.w - h4.w);
                *(float4*)(xh + r * KSP + c4) = h4;
                *(float4*)(xl + r * KSP + c4) = l4;
            } else {
                f -= 512;
                const int r  = f >> 2;
                const int c4 = (f & 3) << 2;
                const int ge = k0 + c4;
                float4 v = make_float4(0.f, 0.f, 0.f, 0.f);
                if (ge + 3 < EDIM) v = *(const float4*)(W + (size_t)r * EDIM + ge);
                float4 h4;
                h4.x = cvtf_tf32(v.x);
                h4.y = cvtf_tf32(v.y);
                h4.z = cvtf_tf32(v.z);
                h4.w = cvtf_tf32(v.w);
                *(float4*)(wh + r * KSP + c4) = h4;
            }
        }
        __syncthreads();

#pragma unroll
        for (int kk = 0; kk < 16; kk += 8) {
            const int ab = (warp * 16 + rl) * KSP + kk + cl;
            unsigned ah0 = __float_as_uint(xh[ab]);
            unsigned ah1 = __float_as_uint(xh[ab + 8 * KSP]);
            unsigned ah2 = __float_as_uint(xh[ab + 4]);
            unsigned ah3 = __float_as_uint(xh[ab + 8 * KSP + 4]);
            unsigned al0 = __float_as_uint(xl[ab]);
            unsigned al1 = __float_as_uint(xl[ab + 8 * KSP]);
            unsigned al2 = __float_as_uint(xl[ab + 4]);
            unsigned al3 = __float_as_uint(xl[ab + 8 * KSP + 4]);
#pragma unroll
            for (int t = 0; t < 16; t++) {
                const int bi = (t * 8 + rl) * KSP + kk + cl;
                unsigned bh0 = __float_as_uint(wh[bi]), bh1 = __float_as_uint(wh[bi + 4]);
                mma8(d[t][0], d[t][1], d[t][2], d[t][3], ah0, ah1, ah2, ah3, bh0, bh1);
                mma8(d[t][0], d[t][1], d[t][2], d[t][3], al0, al1, al2, al3, bh0, bh1);
            }
        }
    }

    const int rlo = row0 + warp * 16 + rl;
    const int rhi = rlo + 8;
#pragma unroll
    for (int t = 0; t < 16; t++) {
        const int c0 = t * 8 + 2 * cl;
        const float b0 = bs[c0], b1 = bs[c0 + 1];
        float2 v0, v1;
        v0.x = cvtf_tf32(fmaxf(d[t][0] + b0, 0.0f));
        v0.y = cvtf_tf32(fmaxf(d[t][1] + b1, 0.0f));
        v1.x = cvtf_tf32(fmaxf(d[t][2] + b0, 0.0f));
        v1.y = cvtf_tf32(fmaxf(d[t][3] + b1, 0.0f));
        *(float2*)(out + (size_t)rlo * HDIM + c0) = v0;
        *(float2*)(out + (size_t)rhi * HDIM + c0) = v1;
    }
}

// ---------------------------------------------------------------------------
// Kernel 2: fused flash attention, tf32 mma, warp-pair split.
// qs rows are shifted by +(q&4) floats so BOTH phase-1 (banks 8(rl&3)+cl+4[rl>=4])
// and phase-2 (banks 8cl+rl, shift==0 for q=k0+cl; +4 const for b1) fragment
// loads are bank-conflict-free.
// ---------------------------------------------------------------------------
#define CSP 132   // mod 32 = 4 -> A frags conflict-free
#define QSP 136   // + (q&4) row shift -> conflict-free both phases
#define PSP 68    // mod 32 = 4 -> phase2 A conflict-free
// floats: cs 64*132=8448, qs 64*136=8704, ps 4*16*68=4352, red 256 -> 21760
#define ATTN_SMEM (21760 * 4 + QSTN * 4)   // 89088 B -> 2 CTAs/SM

__global__ __launch_bounds__(256, 2) void attn_mma(const float* __restrict__ ctxL,
                                                   const float* __restrict__ qstL,
                                                   const int*   __restrict__ mask,
                                                   float* __restrict__ out) {
    extern __shared__ float sm[];
    float* cs   = sm;                     // 64 x 132
    float* qs   = cs + 64 * CSP;          // 64 x 136 (Q and V view, row-shifted)
    float* ps   = qs + 64 * QSP;          // [4 pairs][16 rows][68]
    float* redm = ps + 4 * 16 * PSP;      // [4][2][16] partial row max
    float* reds = redm + 128;             // [4][2][16] partial row sum
    int*   ms   = (int*)(reds + 128);     // 512

    const int tid  = threadIdx.x;
    const int warp = tid >> 5, lane = tid & 31;
    const int rl   = lane >> 2, cl = lane & 3;
    const int pair = warp >> 1, half = warp & 1;
    const int bb   = blockIdx.x >> 6;
    const int ct   = blockIdx.x & 63;
    const int row0 = ct * 64;
    const int r0   = pair * 16;
    float* pr = ps + pair * 16 * PSP;

    const float* cbase = ctxL + ((size_t)bb * CTX + row0) * HDIM;
    const float* qbase = qstL + (size_t)bb * QSTN * HDIM;

    for (int f = tid; f < 2048; f += 256) {
        const int r = f >> 5, h4 = (f & 31) << 2;
        *(float4*)(cs + r * CSP + h4) = *(const float4*)(cbase + (size_t)r * HDIM + h4);
    }
    for (int i = tid; i < QSTN; i += 256) ms[i] = mask[bb * QSTN + i];

    const float NEG_INF = __int_as_float(0xff800000);
    float o[8][4];
#pragma unroll
    for (int t = 0; t < 8; t++)
#pragma unroll
        for (int i = 0; i < 4; i++) o[t][i] = 0.0f;
    float m_lo = NEG_INF, m_hi = NEG_INF, l_lo = 0.0f, l_hi = 0.0f;

    for (int qc = 0; qc < QSTN / 64; qc++) {
        __syncthreads();               // previous chunk fully consumed (qs, ps, red)
        for (int f = tid; f < 2048; f += 256) {
            const int q = f >> 5, h4 = (f & 31) << 2;
            *(float4*)(qs + q * QSP + h4 + (q & 4)) =
                *(const float4*)(qbase + (size_t)qc * 64 * HDIM + (size_t)q * HDIM + h4);
        }
        __syncthreads();

        // ---- phase 1: S[16 x 32] = C @ Q^T (this warp's q half) ----------
        float s[4][4];
#pragma unroll
        for (int t = 0; t < 4; t++)
#pragma unroll
            for (int i = 0; i < 4; i++) s[t][i] = 0.0f;

#pragma unroll
        for (int k0 = 0; k0 < HDIM; k0 += 8) {
            const int ab = (r0 + rl) * CSP + k0 + cl;
            unsigned a0 = __float_as_uint(cs[ab]);
            unsigned a1 = __float_as_uint(cs[ab + 8 * CSP]);
            unsigned a2 = __float_as_uint(cs[ab + 4]);
            unsigned a3 = __float_as_uint(cs[ab + 8 * CSP + 4]);
#pragma unroll
            for (int t = 0; t < 4; t++) {
                // q = half*32 + t*8 + rl  ->  (q & 4) == (rl & 4)
                const int bi = (half * 32 + t * 8 + rl) * QSP + k0 + cl + (rl & 4);
                unsigned b0 = __float_as_uint(qs[bi]);
                unsigned b1 = __float_as_uint(qs[bi + 4]);
                mma8(s[t][0], s[t][1], s[t][2], s[t][3], a0, a1, a2, a3, b0, b1);
            }
        }

        // ---- masked partial row max over this half -----------------------
        const int qb = qc * 64 + half * 32;
        float mx_lo = NEG_INF, mx_hi = NEG_INF;
#pragma unroll
        for (int t = 0; t < 4; t++) {
            const int c0 = t * 8 + 2 * cl;
            const int m0 = ms[qb + c0], m1 = ms[qb + c0 + 1];
            if (m0) { mx_lo = fmaxf(mx_lo, s[t][0]); mx_hi = fmaxf(mx_hi, s[t][2]); }
            if (m1) { mx_lo = fmaxf(mx_lo, s[t][1]); mx_hi = fmaxf(mx_hi, s[t][3]); }
        }
#pragma unroll
        for (int off = 1; off <= 2; off <<= 1) {
            mx_lo = fmaxf(mx_lo, __shfl_xor_sync(0xffffffffu, mx_lo, off));
            mx_hi = fmaxf(mx_hi, __shfl_xor_sync(0xffffffffu, mx_hi, off));
        }
        if (cl == 0) {
            redm[(pair * 2 + half) * 16 + rl]     = mx_lo;
            redm[(pair * 2 + half) * 16 + rl + 8] = mx_hi;
        }
        asm volatile("bar.sync %0, 64;" :: "r"(pair + 1) : "memory");
        mx_lo = fmaxf(mx_lo, redm[(pair * 2 + (1 - half)) * 16 + rl]);
        mx_hi = fmaxf(mx_hi, redm[(pair * 2 + (1 - half)) * 16 + rl + 8]);

        const float mn_lo = fmaxf(m_lo, mx_lo);
        const float mn_hi = fmaxf(m_hi, mx_hi);
        const float sc_lo = (m_lo == NEG_INF) ? 0.0f : __expf(m_lo - mn_lo);
        const float sc_hi = (m_hi == NEG_INF) ? 0.0f : __expf(m_hi - mn_hi);

        // ---- exp, P -> smem (this half's cols), partial sums -------------
        float sum_lo = 0.0f, sum_hi = 0.0f;
#pragma unroll
        for (int t = 0; t < 4; t++) {
            const int c0 = t * 8 + 2 * cl;
            const int m0 = ms[qb + c0], m1 = ms[qb + c0 + 1];
            float p0 = m0 ? cvtf_tf32(__expf(s[t][0] - mn_lo)) : 0.0f;
            float p1 = m1 ? cvtf_tf32(__expf(s[t][1] - mn_lo)) : 0.0f;
            float p2 = m0 ? cvtf_tf32(__expf(s[t][2] - mn_hi)) : 0.0f;
            float p3 = m1 ? cvtf_tf32(__expf(s[t][3] - mn_hi)) : 0.0f;
            sum_lo += p0 + p1;
            sum_hi += p2 + p3;
            const int col = half * 32 + c0;
            *(float2*)(pr + rl * PSP + col)       = make_float2(p0, p1);
            *(float2*)(pr + (rl + 8) * PSP + col) = make_float2(p2, p3);
        }
#pragma unroll
        for (int off = 1; off <= 2; off <<= 1) {
            sum_lo += __shfl_xor_sync(0xffffffffu, sum_lo, off);
            sum_hi += __shfl_xor_sync(0xffffffffu, sum_hi, off);
        }
        if (cl == 0) {
            reds[(pair * 2 + half) * 16 + rl]     = sum_lo;
            reds[(pair * 2 + half) * 16 + rl + 8] = sum_hi;
        }
        asm volatile("bar.sync %0, 64;" :: "r"(pair + 1) : "memory");  // also orders ps
        sum_lo += reds[(pair * 2 + (1 - half)) * 16 + rl];
        sum_hi += reds[(pair * 2 + (1 - half)) * 16 + rl + 8];

        l_lo = l_lo * sc_lo + sum_lo;
        l_hi = l_hi * sc_hi + sum_hi;
        m_lo = mn_lo; m_hi = mn_hi;

#pragma unroll
        for (int t = 0; t < 8; t++) {
            o[t][0] *= sc_lo; o[t][1] *= sc_lo;
            o[t][2] *= sc_hi; o[t][3] *= sc_hi;
        }

        // ---- phase 2: O[16 x 64] += P @ V (this warp's h half) -----------
#pragma unroll
        for (int k0 = 0; k0 < 64; k0 += 8) {
            const int ab = rl * PSP + k0 + cl;
            unsigned a0 = __float_as_uint(pr[ab]);
            unsigned a1 = __float_as_uint(pr[ab + 8 * PSP]);
            unsigned a2 = __float_as_uint(pr[ab + 4]);
            unsigned a3 = __float_as_uint(pr[ab + 8 * PSP + 4]);
#pragma unroll
            for (int t = 0; t < 8; t++) {
                const int hcol = half * 64 + t * 8 + rl;
                // b0: row q=k0+cl   -> shift (q&4)==0; b1: row q=k0+cl+4 -> shift +4
                const int bi0 = (k0 + cl) * QSP + hcol;
                const int bi1 = (k0 + cl + 4) * QSP + hcol + 4;
                unsigned b0 = __float_as_uint(qs[bi0]);
                unsigned b1 = __float_as_uint(qs[bi1]);
                mma8(o[t][0], o[t][1], o[t][2], o[t][3], a0, a1, a2, a3, b0, b1);
            }
        }
    }

    // ---- epilogue: normalize + store -------------------------------------
    const float inv_lo = 1.0f / l_lo;
    const float inv_hi = 1.0f / l_hi;
    float* ob = out + ((size_t)bb * CTX + row0) * HDIM;
    const int rlo = r0 + rl, rhi = rlo + 8;
#pragma unroll
    for (int t = 0; t < 8; t++) {
        const int c0 = half * 64 + t * 8 + 2 * cl;
        *(float2*)(ob + (size_t)rlo * HDIM + c0) =
            make_float2(o[t][0] * inv_lo, o[t][1] * inv_lo);
        *(float2*)(ob + (size_t)rhi * HDIM + c0) =
            make_float2(o[t][2] * inv_hi, o[t][3] * inv_hi);
    }
}

// ---------------------------------------------------------------------------
extern "C" void kernel_launch(void* const* d_in, const int* in_sizes, int n_in,
                              void* d_out, int out_size) {
    const float* ctx  = (const float*)d_in[0];   // [8,4096,300]
    const float* qst  = (const float*)d_in[1];   // [8,512,300]
    const int*   mask = (const int*)d_in[2];     // [8,512]
    const float* W    = (const float*)d_in[3];   // [128,300]
    const float* bias = (const float*)d_in[4];   // [128]
    float*       out  = (float*)d_out;           // [8,4096,128]

    cudaFuncSetAttribute(attn_mma, cudaFuncAttributeMaxDynamicSharedMemorySize, ATTN_SMEM);

    void* p_ctxL = nullptr; void* p_qstL = nullptr;
    cudaGetSymbolAddress(&p_ctxL, g_ctx_logits);
    cudaGetSymbolAddress(&p_qstL, g_qst_logits);
    float* ctxL = (float*)p_ctxL;
    float* qstL = (float*)p_qstL;

    // fused logits: blocks [0,256) ctx rows, [256,288) qst rows
    logits_mma<<<288, 256>>>(ctx, qst, W, bias, ctxL, qstL);

    // fused scores -> online softmax -> AV (64 ctx rows, 8 warps per block)
    attn_mma<<<BBATCH * (CTX / 64), 256, ATTN_SMEM>>>(ctxL, qstL, mask, out);
}